// round 3
// baseline (speedup 1.0000x reference)
#include <cuda_runtime.h>

// Problem constants
// B=2, S=2048, D=1024, H=16, HS=64
// Key identity used: no softmax and Q==V  =>  out = V @ (K^T @ V) / 8  per (b,h)
// K^T V is only 64x64, so the O(S^2) attention collapses to two tiny GEMMs.

#define S_LEN 2048
#define D_DIM 1024
#define N_H   16
#define HS    64
#define BH    32           // B*H
#define MROWS 4096         // B*S

// ---------------- scratch (no allocs allowed) ----------------
__device__ float g_K[BH * S_LEN * HS];        // [B,H,S,HS]  16 MB
__device__ float g_V[BH * S_LEN * HS];        // [B,H,S,HS]  16 MB
__device__ float g_Mpart[BH * 8 * HS * HS];   // split-S partials, 4 MB
__device__ float g_M[BH * HS * HS];           // K^T V / 8,   0.5 MB
__device__ float g_A[MROWS * D_DIM];          // concat heads, 16 MB

// =============================================================
// Kernel 1: KV projection.  C[4096, 2048] = X[4096,1024] @ [Wk|Wv]
// Wk/Wv layout: [H, D, HS] -> W[h*D*HS + d*HS + e]
// Writes K,V as [B,H,S,HS].
// 128x128x16 tile, 256 threads, 8x8 microtile.
// =============================================================
__global__ __launch_bounds__(256) void k1_proj(const float* __restrict__ x,
                                               const float* __restrict__ Wk,
                                               const float* __restrict__ Wv)
{
    __shared__ float As[16][132];   // padded, transposed A tile
    __shared__ float Bs[16][128];
    const int bm = blockIdx.y * 128;
    const int bn = blockIdx.x * 128;
    const int tid = threadIdx.x;
    const int tx = tid & 15, ty = tid >> 4;

    float acc[8][8] = {};

    for (int k0 = 0; k0 < D_DIM; k0 += 16) {
        // load A tile (128 x 16), transposed into As[c][r]
        #pragma unroll
        for (int i = 0; i < 8; i++) {
            int idx = tid + i * 256;
            int r = idx >> 4, c = idx & 15;
            As[c][r] = x[(bm + r) * D_DIM + k0 + c];
        }
        // load B tile (16 x 128): column gj of [Wk|Wv]
        #pragma unroll
        for (int i = 0; i < 8; i++) {
            int idx = tid + i * 256;
            int c = idx >> 7, j = idx & 127;
            int gj = bn + j;
            int jp = gj & 1023;
            const float* W = (gj < 1024) ? Wk : Wv;   // uniform per block (bn%1024 tiles of 128)
            Bs[c][j] = W[(jp >> 6) * (D_DIM * HS) + (k0 + c) * HS + (jp & 63)];
        }
        __syncthreads();
        #pragma unroll
        for (int c = 0; c < 16; c++) {
            float4 a0 = *(const float4*)&As[c][ty * 8];
            float4 a1 = *(const float4*)&As[c][ty * 8 + 4];
            float4 b0 = *(const float4*)&Bs[c][tx * 8];
            float4 b1 = *(const float4*)&Bs[c][tx * 8 + 4];
            float a[8] = {a0.x, a0.y, a0.z, a0.w, a1.x, a1.y, a1.z, a1.w};
            float b[8] = {b0.x, b0.y, b0.z, b0.w, b1.x, b1.y, b1.z, b1.w};
            #pragma unroll
            for (int i = 0; i < 8; i++)
                #pragma unroll
                for (int j = 0; j < 8; j++)
                    acc[i][j] += a[i] * b[j];
        }
        __syncthreads();
    }

    // scatter to K/V in [B,H,S,HS]
    #pragma unroll
    for (int i = 0; i < 8; i++) {
        int m = bm + ty * 8 + i;
        int b = m >> 11, s = m & 2047;
        #pragma unroll
        for (int j = 0; j < 8; j++) {
            int gj = bn + tx * 8 + j;
            int jp = gj & 1023;
            float* dst = (gj < 1024) ? g_K : g_V;
            dst[(((b << 4) + (jp >> 6)) * S_LEN + s) * HS + (jp & 63)] = acc[i][j];
        }
    }
}

// =============================================================
// Kernel 2: per-(b,h) partial M = K^T V over an S-chunk of 256 rows.
// grid (32, 8), 256 threads, each thread 4x4 of the 64x64 output.
// =============================================================
__global__ __launch_bounds__(256) void k2_kv()
{
    const int bh = blockIdx.x;
    const int sc = blockIdx.y;
    const float* K = g_K + (bh * S_LEN + sc * 256) * HS;
    const float* V = g_V + (bh * S_LEN + sc * 256) * HS;

    __shared__ float Ks[32][64];
    __shared__ float Vs[32][64];
    const int tid = threadIdx.x;
    const int tx = tid & 15, ty = tid >> 4;

    float acc[4][4] = {};

    for (int s0 = 0; s0 < 256; s0 += 32) {
        #pragma unroll
        for (int i = tid; i < 32 * 64; i += 256) {
            Ks[i >> 6][i & 63] = K[(s0 + (i >> 6)) * HS + (i & 63)];
            Vs[i >> 6][i & 63] = V[(s0 + (i >> 6)) * HS + (i & 63)];
        }
        __syncthreads();
        #pragma unroll
        for (int s = 0; s < 32; s++) {
            float a[4], b[4];
            #pragma unroll
            for (int i = 0; i < 4; i++) a[i] = Ks[s][ty * 4 + i];
            #pragma unroll
            for (int j = 0; j < 4; j++) b[j] = Vs[s][tx * 4 + j];
            #pragma unroll
            for (int i = 0; i < 4; i++)
                #pragma unroll
                for (int j = 0; j < 4; j++)
                    acc[i][j] += a[i] * b[j];
        }
        __syncthreads();
    }

    float* P = g_Mpart + (bh * 8 + sc) * (HS * HS);
    #pragma unroll
    for (int i = 0; i < 4; i++)
        #pragma unroll
        for (int j = 0; j < 4; j++)
            P[(ty * 4 + i) * HS + tx * 4 + j] = acc[i][j];
}

// Reduce the 8 S-chunks and fold the 1/sqrt(HS)=1/8 scale.
__global__ __launch_bounds__(256) void k2_reduce()
{
    int i = blockIdx.x * 256 + threadIdx.x;   // 0 .. 131071
    int bh = i >> 12;
    int o  = i & 4095;
    float s = 0.f;
    #pragma unroll
    for (int c = 0; c < 8; c++)
        s += g_Mpart[(bh * 8 + c) * 4096 + o];
    g_M[i] = s * 0.125f;
}

// =============================================================
// Kernel 3: A[b,s, h*64+f] = sum_e V[b,h,s,e] * M[b,h,e,f]
// grid (32, 16), 128 threads; one row of V per thread, M staged in smem.
// =============================================================
__global__ __launch_bounds__(128) void k3_av()
{
    const int bh = blockIdx.x;
    const int s  = blockIdx.y * 128 + threadIdx.x;

    __shared__ float Ms[64][64];
    for (int i = threadIdx.x; i < 4096; i += 128)
        Ms[i >> 6][i & 63] = g_M[bh * 4096 + i];
    __syncthreads();

    const float* Vrow = g_V + (bh * S_LEN + s) * HS;
    float acc[64] = {};
    #pragma unroll 4
    for (int e = 0; e < 64; e++) {
        float ve = Vrow[e];
        #pragma unroll
        for (int f = 0; f < 64; f += 4) {
            float4 m4 = *(const float4*)&Ms[e][f];
            acc[f + 0] += ve * m4.x;
            acc[f + 1] += ve * m4.y;
            acc[f + 2] += ve * m4.z;
            acc[f + 3] += ve * m4.w;
        }
    }

    const int b = bh >> 4, h = bh & 15;
    float* Arow = g_A + ((b * S_LEN + s) * D_DIM) + h * HS;
    #pragma unroll
    for (int f = 0; f < 64; f += 4)
        *(float4*)&Arow[f] = make_float4(acc[f], acc[f + 1], acc[f + 2], acc[f + 3]);
}

// =============================================================
// Kernel 4: Y[4096,1024] = A @ Wproj + bproj
// Wproj row-major [1024,1024]: Y[m,n] = sum_k A[m,k]*Wproj[k*1024+n]
// =============================================================
__global__ __launch_bounds__(256) void k4_out(const float* __restrict__ Wp,
                                              const float* __restrict__ bp,
                                              float* __restrict__ Y)
{
    __shared__ float As[16][132];
    __shared__ float Bs[16][128];
    const int bm = blockIdx.y * 128;
    const int bn = blockIdx.x * 128;
    const int tid = threadIdx.x;
    const int tx = tid & 15, ty = tid >> 4;

    float acc[8][8] = {};

    for (int k0 = 0; k0 < D_DIM; k0 += 16) {
        #pragma unroll
        for (int i = 0; i < 8; i++) {
            int idx = tid + i * 256;
            int r = idx >> 4, c = idx & 15;
            As[c][r] = g_A[(bm + r) * D_DIM + k0 + c];
        }
        #pragma unroll
        for (int i = 0; i < 8; i++) {
            int idx = tid + i * 256;
            int c = idx >> 7, j = idx & 127;
            Bs[c][j] = Wp[(k0 + c) * D_DIM + bn + j];
        }
        __syncthreads();
        #pragma unroll
        for (int c = 0; c < 16; c++) {
            float4 a0 = *(const float4*)&As[c][ty * 8];
            float4 a1 = *(const float4*)&As[c][ty * 8 + 4];
            float4 b0 = *(const float4*)&Bs[c][tx * 8];
            float4 b1 = *(const float4*)&Bs[c][tx * 8 + 4];
            float a[8] = {a0.x, a0.y, a0.z, a0.w, a1.x, a1.y, a1.z, a1.w};
            float b[8] = {b0.x, b0.y, b0.z, b0.w, b1.x, b1.y, b1.z, b1.w};
            #pragma unroll
            for (int i = 0; i < 8; i++)
                #pragma unroll
                for (int j = 0; j < 8; j++)
                    acc[i][j] += a[i] * b[j];
        }
        __syncthreads();
    }

    #pragma unroll
    for (int i = 0; i < 8; i++) {
        int m = bm + ty * 8 + i;
        #pragma unroll
        for (int j = 0; j < 8; j++) {
            int gn = bn + tx * 8 + j;
            Y[m * D_DIM + gn] = acc[i][j] + bp[gn];
        }
    }
}

// =============================================================
extern "C" void kernel_launch(void* const* d_in, const int* in_sizes, int n_in,
                              void* d_out, int out_size)
{
    const float* x   = (const float*)d_in[0];
    const float* Wk  = (const float*)d_in[1];
    const float* Wv  = (const float*)d_in[2];
    const float* Wp  = (const float*)d_in[3];
    const float* bp  = (const float*)d_in[4];
    float* Y = (float*)d_out;

    k1_proj  <<<dim3(16, 32), 256>>>(x, Wk, Wv);   // KV projection
    k2_kv    <<<dim3(32, 8), 256>>>();             // partial K^T V
    k2_reduce<<<512, 256>>>();                     // reduce + scale
    k3_av    <<<dim3(32, 16), 128>>>();            // V @ M
    k4_out   <<<dim3(8, 32), 256>>>(Wp, bp, Y);    // output projection + bias
}

// round 7
// speedup vs baseline: 2.8658x; 2.8658x over previous
#include <cuda_runtime.h>

// B=2, S=2048, D=1024, H=16, HS=64
// out = V @ (K^T @ V) / 8 per (b,h)   (no softmax, Q==V)
// Tensor path: mma.sync.m16n8k8 tf32 (valid on plain sm_103) + cp.async.
// R6 bug fixed: __device__ scratch symbols must NOT be passed as kernel args
// from host code (host shadow address != device address). Pointers are now
// selected inside the kernel from `mode`.

#define S_LEN 2048
#define D_DIM 1024
#define HS    64
#define BH    32
#define MROWS 4096

// ---------------- scratch (no allocs allowed) ----------------
__device__ float g_K[BH * S_LEN * HS];        // [B,H,S,HS]
__device__ float g_V[BH * S_LEN * HS];        // [B,H,S,HS]
__device__ float g_Mpart[BH * 8 * HS * HS];
__device__ float g_M[BH * HS * HS];
__device__ float g_A[MROWS * D_DIM];          // concat heads (tf32-rounded)
__device__ float g_Xtf[MROWS * D_DIM];        // x tf32-rounded
__device__ float g_Wt[2048 * 1024];           // [Wk|Wv] K-major rows (tf32-rounded)
__device__ float g_Wpt[1024 * 1024];          // Wproj^T K-major rows (tf32-rounded)

// =============================================================
// helpers
// =============================================================
__device__ __forceinline__ float f2tf32(float f) {
    unsigned u;
    asm("cvt.rna.tf32.f32 %0, %1;" : "=r"(u) : "f"(f));
    return __uint_as_float(u);
}

__device__ __forceinline__ void cp16(void* dst, const void* src) {
    unsigned d;
    asm("{ .reg .u64 t; cvta.to.shared.u64 t, %1; cvt.u32.u64 %0, t; }"
        : "=r"(d) : "l"(dst));
    asm volatile("cp.async.cg.shared.global [%0], [%1], 16;" :: "r"(d), "l"(src));
}

__device__ __forceinline__ void mma8(float* d, const float* a, const float* b) {
    asm volatile(
        "mma.sync.aligned.m16n8k8.row.col.f32.tf32.tf32.f32 "
        "{%0,%1,%2,%3}, {%4,%5,%6,%7}, {%8,%9}, {%0,%1,%2,%3};"
        : "+f"(d[0]), "+f"(d[1]), "+f"(d[2]), "+f"(d[3])
        : "r"(__float_as_uint(a[0])), "r"(__float_as_uint(a[1])),
          "r"(__float_as_uint(a[2])), "r"(__float_as_uint(a[3])),
          "r"(__float_as_uint(b[0])), "r"(__float_as_uint(b[1])));
}

// =============================================================
// x -> tf32-rounded copy
// =============================================================
__global__ __launch_bounds__(256) void xcvt(const float* __restrict__ x)
{
    int i = (blockIdx.x * 256 + threadIdx.x) * 4;
    float4 v = *(const float4*)(x + i);
    *(float4*)(g_Xtf + i) = make_float4(f2tf32(v.x), f2tf32(v.y),
                                        f2tf32(v.z), f2tf32(v.w));
}

// =============================================================
// Weight transposes -> K-major rows, tf32-rounded
// =============================================================
__global__ __launch_bounds__(256) void tW(const float* __restrict__ Wk,
                                          const float* __restrict__ Wv)
{
    __shared__ float tile[32][33];
    const int hh = blockIdx.z;
    const int x0 = blockIdx.x * 32;         // d tile
    const int y0 = blockIdx.y * 32;         // e tile
    const int tx = threadIdx.x, ty = threadIdx.y;
    const float* W = (hh < 16) ? Wk : Wv;
    const int h = hh & 15;
    #pragma unroll
    for (int j = 0; j < 4; j++)
        tile[ty + 8 * j][tx] = W[h * 65536 + (x0 + ty + 8 * j) * 64 + y0 + tx];
    __syncthreads();
    #pragma unroll
    for (int j = 0; j < 4; j++)
        g_Wt[(hh * 64 + y0 + ty + 8 * j) * 1024 + x0 + tx] = f2tf32(tile[tx][ty + 8 * j]);
}

__global__ __launch_bounds__(256) void tWp(const float* __restrict__ Wp)
{
    __shared__ float tile[32][33];
    const int x0 = blockIdx.x * 32;   // n tile
    const int y0 = blockIdx.y * 32;   // k tile
    const int tx = threadIdx.x, ty = threadIdx.y;
    #pragma unroll
    for (int j = 0; j < 4; j++)
        tile[ty + 8 * j][tx] = Wp[(y0 + ty + 8 * j) * 1024 + x0 + tx];
    __syncthreads();
    #pragma unroll
    for (int j = 0; j < 4; j++)
        g_Wpt[(x0 + ty + 8 * j) * 1024 + y0 + tx] = f2tf32(tile[tx][ty + 8 * j]);
}

// =============================================================
// tf32 mma.sync GEMM: C[4096, N] = A[4096,1024] @ B^T  (B = K-major rows)
// BM=128, BN=256, BK=32, 3-stage cp.async pipeline, 256 thr, warp tile 64x64.
// Smem rows padded to 36 floats -> fragment LDS bank (4g+tg)%32 conflict-free.
// mode 0: A=g_Xtf, B=g_Wt, scatter K/V.  mode 1: A=g_A, B=g_Wpt, Y + bias.
// =============================================================
#define BMt 128
#define BNt 256
#define BKt 32
#define PITCH 36
#define SA_BYTES (BMt * PITCH * 4)             // 18432
#define SB_BYTES (BNt * PITCH * 4)             // 36864
#define STAGE_BYTES (SA_BYTES + SB_BYTES)      // 55296
#define GEMM_SMEM (3 * STAGE_BYTES)            // 165888

__global__ __launch_bounds__(256, 1)
void gemm_mma(const float* __restrict__ bias,
              float* __restrict__ Y,
              int mode)
{
    extern __shared__ __align__(16) char sm[];
    const int tid = threadIdx.x, wid = tid >> 5, lane = tid & 31;
    const int g = lane >> 2, tg = lane & 3;
    const int bm = blockIdx.y * BMt, bn = blockIdx.x * BNt;

    // device-side pointer selection (device symbols are valid here)
    const float* Ag = ((mode == 0) ? g_Xtf : g_A) + (size_t)bm * 1024;
    const float* Bg = ((mode == 0) ? g_Wt : g_Wpt) + (size_t)bn * 1024;

    // ---- prefetch one BK chunk into stage slot ----
    auto prefetch = [&](int kc) {
        char* sA = sm + (kc % 3) * STAGE_BYTES;
        char* sB = sA + SA_BYTES;
        const float* As = Ag + kc * BKt;
        const float* Bs = Bg + kc * BKt;
        #pragma unroll
        for (int i = 0; i < 4; i++) {
            int idx = tid + i * 256;
            int m = idx >> 3, k4 = idx & 7;
            cp16(sA + m * (PITCH * 4) + k4 * 16, As + (size_t)m * 1024 + k4 * 4);
        }
        #pragma unroll
        for (int i = 0; i < 8; i++) {
            int idx = tid + i * 256;
            int n = idx >> 3, k4 = idx & 7;
            cp16(sB + n * (PITCH * 4) + k4 * 16, Bs + (size_t)n * 1024 + k4 * 4);
        }
        asm volatile("cp.async.commit_group;" ::: "memory");
    };

    prefetch(0); prefetch(1); prefetch(2);

    const int wm = (wid & 1) * 64;       // 2 warps along M
    const int wn = (wid >> 1) * 64;      // 4 warps along N

    float acc[4][8][4];
    #pragma unroll
    for (int mt = 0; mt < 4; mt++)
        #pragma unroll
        for (int nt = 0; nt < 8; nt++)
            #pragma unroll
            for (int q = 0; q < 4; q++) acc[mt][nt][q] = 0.f;

    for (int kc = 0; kc < 32; kc++) {
        const float* sA = (const float*)(sm + (kc % 3) * STAGE_BYTES);
        const float* sB = (const float*)((const char*)sA + SA_BYTES);
        asm volatile("cp.async.wait_group 2;" ::: "memory");
        __syncthreads();

        #pragma unroll
        for (int ks = 0; ks < 4; ks++) {
            const int k = ks * 8 + tg;
            float a[4][4], b[8][2];
            #pragma unroll
            for (int mt = 0; mt < 4; mt++) {
                const float* p = sA + (wm + mt * 16 + g) * PITCH + k;
                a[mt][0] = p[0];
                a[mt][1] = p[8 * PITCH];
                a[mt][2] = p[4];
                a[mt][3] = p[8 * PITCH + 4];
            }
            #pragma unroll
            for (int nt = 0; nt < 8; nt++) {
                const float* p = sB + (wn + nt * 8 + g) * PITCH + k;
                b[nt][0] = p[0];
                b[nt][1] = p[4];
            }
            #pragma unroll
            for (int mt = 0; mt < 4; mt++)
                #pragma unroll
                for (int nt = 0; nt < 8; nt++)
                    mma8(acc[mt][nt], a[mt], b[nt]);
        }
        __syncthreads();
        if (kc + 3 < 32) prefetch(kc + 3);
    }

    // ---- epilogue ----
    // C fragment: c0 (row g, col 2tg), c1 (+1), c2 (row g+8, col 2tg), c3 (+1)
    const int gnw = bn + wn;                 // warp's 64-col span = exactly 1 head
    if (mode == 0) {
        const int isK = (gnw < 1024);
        const int h = (gnw & 1023) >> 6;
        float* base = (isK ? g_K : g_V);
        #pragma unroll
        for (int mt = 0; mt < 4; mt++) {
            const int m0 = bm + wm + mt * 16 + g;
            #pragma unroll
            for (int half = 0; half < 2; half++) {
                const int m = m0 + half * 8;
                const int b = m >> 11, s = m & 2047;
                float* dst = base + (size_t)((b * 16 + h) * 2048 + s) * 64;
                #pragma unroll
                for (int nt = 0; nt < 8; nt++) {
                    const int e = nt * 8 + tg * 2;
                    *(float2*)(dst + e) = make_float2(acc[mt][nt][half * 2],
                                                      acc[mt][nt][half * 2 + 1]);
                }
            }
        }
    } else {
        #pragma unroll
        for (int mt = 0; mt < 4; mt++) {
            const int m0 = bm + wm + mt * 16 + g;
            #pragma unroll
            for (int half = 0; half < 2; half++) {
                const int m = m0 + half * 8;
                float* dst = Y + (size_t)m * 1024;
                #pragma unroll
                for (int nt = 0; nt < 8; nt++) {
                    const int gn = gnw + nt * 8 + tg * 2;
                    float2 bb = *(const float2*)(bias + gn);
                    *(float2*)(dst + gn) = make_float2(acc[mt][nt][half * 2] + bb.x,
                                                       acc[mt][nt][half * 2 + 1] + bb.y);
                }
            }
        }
    }
}

// =============================================================
// Kernel 2: per-(b,h) partial M = K^T V over an S-chunk of 256 rows.
// =============================================================
__global__ __launch_bounds__(256) void k2_kv()
{
    const int bh = blockIdx.x;
    const int sc = blockIdx.y;
    const float* K = g_K + (bh * S_LEN + sc * 256) * HS;
    const float* V = g_V + (bh * S_LEN + sc * 256) * HS;

    __shared__ float Ks[32][64];
    __shared__ float Vs[32][64];
    const int tid = threadIdx.x;
    const int tx = tid & 15, ty = tid >> 4;

    float acc[4][4] = {};

    for (int s0 = 0; s0 < 256; s0 += 32) {
        #pragma unroll
        for (int i = tid; i < 32 * 64; i += 256) {
            Ks[i >> 6][i & 63] = K[(s0 + (i >> 6)) * HS + (i & 63)];
            Vs[i >> 6][i & 63] = V[(s0 + (i >> 6)) * HS + (i & 63)];
        }
        __syncthreads();
        #pragma unroll
        for (int s = 0; s < 32; s++) {
            float a[4], b[4];
            #pragma unroll
            for (int i = 0; i < 4; i++) a[i] = Ks[s][ty * 4 + i];
            #pragma unroll
            for (int j = 0; j < 4; j++) b[j] = Vs[s][tx * 4 + j];
            #pragma unroll
            for (int i = 0; i < 4; i++)
                #pragma unroll
                for (int j = 0; j < 4; j++)
                    acc[i][j] += a[i] * b[j];
        }
        __syncthreads();
    }

    float* P = g_Mpart + (bh * 8 + sc) * (HS * HS);
    #pragma unroll
    for (int i = 0; i < 4; i++)
        #pragma unroll
        for (int j = 0; j < 4; j++)
            P[(ty * 4 + i) * HS + tx * 4 + j] = acc[i][j];
}

__global__ __launch_bounds__(256) void k2_reduce()
{
    int i = blockIdx.x * 256 + threadIdx.x;
    int bh = i >> 12;
    int o  = i & 4095;
    float s = 0.f;
    #pragma unroll
    for (int c = 0; c < 8; c++)
        s += g_Mpart[(bh * 8 + c) * 4096 + o];
    g_M[i] = s * 0.125f;
}

// =============================================================
// Kernel 3: A[b,s,h*64+f] = sum_e V[b,h,s,e] * M[b,h,e,f]  (store tf32-rounded)
// =============================================================
__global__ __launch_bounds__(256) void k3_av()
{
    const int bh = blockIdx.x;
    const int tid = threadIdx.x;
    const int row = tid >> 1, half = tid & 1;
    const int s = blockIdx.y * 128 + row;

    __shared__ float Ms[64][64];
    for (int i = tid; i < 4096; i += 256)
        Ms[i >> 6][i & 63] = g_M[bh * 4096 + i];
    __syncthreads();

    const float* Vrow = g_V + (bh * S_LEN + s) * HS;
    const int f0 = half * 32;
    float acc[32] = {};
    #pragma unroll 4
    for (int e = 0; e < 64; e++) {
        float ve = Vrow[e];
        #pragma unroll
        for (int f = 0; f < 32; f += 4) {
            float4 m4 = *(const float4*)&Ms[e][f0 + f];
            acc[f + 0] += ve * m4.x;
            acc[f + 1] += ve * m4.y;
            acc[f + 2] += ve * m4.z;
            acc[f + 3] += ve * m4.w;
        }
    }

    const int b = bh >> 4, h = bh & 15;
    float* Arow = g_A + ((b * S_LEN + s) * D_DIM) + h * HS + f0;
    #pragma unroll
    for (int f = 0; f < 32; f += 4)
        *(float4*)&Arow[f] = make_float4(f2tf32(acc[f]), f2tf32(acc[f + 1]),
                                         f2tf32(acc[f + 2]), f2tf32(acc[f + 3]));
}

// =============================================================
extern "C" void kernel_launch(void* const* d_in, const int* in_sizes, int n_in,
                              void* d_out, int out_size)
{
    const float* x   = (const float*)d_in[0];
    const float* Wk  = (const float*)d_in[1];
    const float* Wv  = (const float*)d_in[2];
    const float* Wp  = (const float*)d_in[3];
    const float* bp  = (const float*)d_in[4];
    float* Y = (float*)d_out;

    cudaFuncSetAttribute(gemm_mma, cudaFuncAttributeMaxDynamicSharedMemorySize, GEMM_SMEM);

    xcvt<<<4096, 256>>>(x);                            // x -> tf32
    tW  <<<dim3(32, 2, 32), dim3(32, 8)>>>(Wk, Wv);    // [Wk|Wv] -> K-major tf32
    tWp <<<dim3(32, 32),    dim3(32, 8)>>>(Wp);        // Wproj^T -> K-major tf32

    gemm_mma<<<dim3(8, 32), 256, GEMM_SMEM>>>(bp, Y, 0);   // K,V projection
    k2_kv    <<<dim3(32, 8), 256>>>();                     // partial K^T V
    k2_reduce<<<512, 256>>>();                             // reduce + scale
    k3_av    <<<dim3(32, 16), 256>>>();                    // V @ M -> g_A
    gemm_mma<<<dim3(4, 32), 256, GEMM_SMEM>>>(bp, Y, 1);   // Y = A@Wp + b
}

// round 8
// speedup vs baseline: 3.3572x; 1.1715x over previous
#include <cuda_runtime.h>

// B=2, S=2048, D=1024, H=16, HS=64
// out = V @ (K^T @ V) / 8 per (b,h)   (no softmax, Q==V)
// mma.sync m16n8k8 tf32 + cp.async. This round: occ-2 GEMM tiles (128x128),
// tensor-core k3 (V@M), float4 k2.

#define S_LEN 2048
#define D_DIM 1024
#define HS    64
#define BH    32
#define MROWS 4096

// ---------------- scratch (no allocs allowed) ----------------
__device__ float g_K[BH * S_LEN * HS];        // [B,H,S,HS] fp32
__device__ float g_V[BH * S_LEN * HS];        // [B,H,S,HS] fp32
__device__ float g_Mpart[BH * 8 * HS * HS];
__device__ float g_M[BH * HS * HS];
__device__ float g_A[MROWS * D_DIM];          // concat heads (tf32-rounded)
__device__ float g_Xtf[MROWS * D_DIM];        // x tf32-rounded
__device__ float g_Wt[2048 * 1024];           // [Wk|Wv] K-major rows (tf32)
__device__ float g_Wpt[1024 * 1024];          // Wproj^T K-major rows (tf32)

// =============================================================
// helpers
// =============================================================
__device__ __forceinline__ float f2tf32(float f) {
    unsigned u;
    asm("cvt.rna.tf32.f32 %0, %1;" : "=r"(u) : "f"(f));
    return __uint_as_float(u);
}

__device__ __forceinline__ void cp16(void* dst, const void* src) {
    unsigned d;
    asm("{ .reg .u64 t; cvta.to.shared.u64 t, %1; cvt.u32.u64 %0, t; }"
        : "=r"(d) : "l"(dst));
    asm volatile("cp.async.cg.shared.global [%0], [%1], 16;" :: "r"(d), "l"(src));
}

__device__ __forceinline__ void mma8(float* d, const float* a, const float* b) {
    asm volatile(
        "mma.sync.aligned.m16n8k8.row.col.f32.tf32.tf32.f32 "
        "{%0,%1,%2,%3}, {%4,%5,%6,%7}, {%8,%9}, {%0,%1,%2,%3};"
        : "+f"(d[0]), "+f"(d[1]), "+f"(d[2]), "+f"(d[3])
        : "r"(__float_as_uint(a[0])), "r"(__float_as_uint(a[1])),
          "r"(__float_as_uint(a[2])), "r"(__float_as_uint(a[3])),
          "r"(__float_as_uint(b[0])), "r"(__float_as_uint(b[1])));
}

// =============================================================
// x -> tf32-rounded copy
// =============================================================
__global__ __launch_bounds__(256) void xcvt(const float* __restrict__ x)
{
    int i = (blockIdx.x * 256 + threadIdx.x) * 4;
    float4 v = *(const float4*)(x + i);
    *(float4*)(g_Xtf + i) = make_float4(f2tf32(v.x), f2tf32(v.y),
                                        f2tf32(v.z), f2tf32(v.w));
}

// =============================================================
// Weight transposes -> K-major rows, tf32-rounded
// =============================================================
__global__ __launch_bounds__(256) void tW(const float* __restrict__ Wk,
                                          const float* __restrict__ Wv)
{
    __shared__ float tile[32][33];
    const int hh = blockIdx.z;
    const int x0 = blockIdx.x * 32;         // d tile
    const int y0 = blockIdx.y * 32;         // e tile
    const int tx = threadIdx.x, ty = threadIdx.y;
    const float* W = (hh < 16) ? Wk : Wv;
    const int h = hh & 15;
    #pragma unroll
    for (int j = 0; j < 4; j++)
        tile[ty + 8 * j][tx] = W[h * 65536 + (x0 + ty + 8 * j) * 64 + y0 + tx];
    __syncthreads();
    #pragma unroll
    for (int j = 0; j < 4; j++)
        g_Wt[(hh * 64 + y0 + ty + 8 * j) * 1024 + x0 + tx] = f2tf32(tile[tx][ty + 8 * j]);
}

__global__ __launch_bounds__(256) void tWp(const float* __restrict__ Wp)
{
    __shared__ float tile[32][33];
    const int x0 = blockIdx.x * 32;   // n tile
    const int y0 = blockIdx.y * 32;   // k tile
    const int tx = threadIdx.x, ty = threadIdx.y;
    #pragma unroll
    for (int j = 0; j < 4; j++)
        tile[ty + 8 * j][tx] = Wp[(y0 + ty + 8 * j) * 1024 + x0 + tx];
    __syncthreads();
    #pragma unroll
    for (int j = 0; j < 4; j++)
        g_Wpt[(x0 + ty + 8 * j) * 1024 + y0 + tx] = f2tf32(tile[tx][ty + 8 * j]);
}

// =============================================================
// tf32 mma.sync GEMM: C[4096, N] = A[4096,1024] @ B^T  (B = K-major rows)
// BM=128, BN=128, BK=32, 3-stage cp.async, 256 thr (8 warps), warp 32x64.
// 108KB smem + <=128 regs -> 2 CTAs/SM (the round's main lever).
// mode 0: A=g_Xtf, B=g_Wt, scatter K/V.  mode 1: A=g_A, B=g_Wpt, Y + bias.
// =============================================================
#define BMt 128
#define BNt 128
#define BKt 32
#define PITCH 36                               // 36 % 32 == 4 -> banks 4g+tg
#define SA_BYTES (BMt * PITCH * 4)             // 18432
#define SB_BYTES (BNt * PITCH * 4)             // 18432
#define STAGE_BYTES (SA_BYTES + SB_BYTES)      // 36864
#define GEMM_SMEM (3 * STAGE_BYTES)            // 110592

__global__ __launch_bounds__(256, 2)
void gemm_mma(const float* __restrict__ bias,
              float* __restrict__ Y,
              int mode)
{
    extern __shared__ __align__(16) char sm[];
    const int tid = threadIdx.x, wid = tid >> 5, lane = tid & 31;
    const int g = lane >> 2, tg = lane & 3;
    const int bm = blockIdx.y * BMt, bn = blockIdx.x * BNt;

    const float* Ag = ((mode == 0) ? g_Xtf : g_A) + (size_t)bm * 1024;
    const float* Bg = ((mode == 0) ? g_Wt : g_Wpt) + (size_t)bn * 1024;

    auto prefetch = [&](int kc) {
        char* sA = sm + (kc % 3) * STAGE_BYTES;
        char* sB = sA + SA_BYTES;
        const float* As = Ag + kc * BKt;
        const float* Bs = Bg + kc * BKt;
        #pragma unroll
        for (int i = 0; i < 4; i++) {
            int idx = tid + i * 256;
            int m = idx >> 3, k4 = idx & 7;
            cp16(sA + m * (PITCH * 4) + k4 * 16, As + (size_t)m * 1024 + k4 * 4);
        }
        #pragma unroll
        for (int i = 0; i < 4; i++) {
            int idx = tid + i * 256;
            int n = idx >> 3, k4 = idx & 7;
            cp16(sB + n * (PITCH * 4) + k4 * 16, Bs + (size_t)n * 1024 + k4 * 4);
        }
        asm volatile("cp.async.commit_group;" ::: "memory");
    };

    prefetch(0); prefetch(1); prefetch(2);

    const int wm = (wid & 3) * 32;       // 4 warps along M
    const int wn = (wid >> 2) * 64;      // 2 warps along N

    float acc[2][8][4];
    #pragma unroll
    for (int mt = 0; mt < 2; mt++)
        #pragma unroll
        for (int nt = 0; nt < 8; nt++)
            #pragma unroll
            for (int q = 0; q < 4; q++) acc[mt][nt][q] = 0.f;

    for (int kc = 0; kc < 32; kc++) {
        const float* sA = (const float*)(sm + (kc % 3) * STAGE_BYTES);
        const float* sB = (const float*)((const char*)sA + SA_BYTES);
        asm volatile("cp.async.wait_group 2;" ::: "memory");
        __syncthreads();

        #pragma unroll
        for (int ks = 0; ks < 4; ks++) {
            const int k = ks * 8 + tg;
            float a[2][4], b[8][2];
            #pragma unroll
            for (int mt = 0; mt < 2; mt++) {
                const float* p = sA + (wm + mt * 16 + g) * PITCH + k;
                a[mt][0] = p[0];
                a[mt][1] = p[8 * PITCH];
                a[mt][2] = p[4];
                a[mt][3] = p[8 * PITCH + 4];
            }
            #pragma unroll
            for (int nt = 0; nt < 8; nt++) {
                const float* p = sB + (wn + nt * 8 + g) * PITCH + k;
                b[nt][0] = p[0];
                b[nt][1] = p[4];
            }
            #pragma unroll
            for (int mt = 0; mt < 2; mt++)
                #pragma unroll
                for (int nt = 0; nt < 8; nt++)
                    mma8(acc[mt][nt], a[mt], b[nt]);
        }
        __syncthreads();
        if (kc + 3 < 32) prefetch(kc + 3);
    }

    // ---- epilogue ----
    // C frag: c0 (row g, col 2tg), c1 (+1), c2 (row g+8, col 2tg), c3 (+1)
    const int gnw = bn + wn;                 // 64-aligned -> exactly 1 head
    if (mode == 0) {
        const int isK = (gnw < 1024);
        const int h = (gnw & 1023) >> 6;
        float* base = (isK ? g_K : g_V);
        #pragma unroll
        for (int mt = 0; mt < 2; mt++) {
            const int m0 = bm + wm + mt * 16 + g;
            #pragma unroll
            for (int half = 0; half < 2; half++) {
                const int m = m0 + half * 8;
                const int b = m >> 11, s = m & 2047;
                float* dst = base + (size_t)((b * 16 + h) * 2048 + s) * 64;
                #pragma unroll
                for (int nt = 0; nt < 8; nt++) {
                    const int e = nt * 8 + tg * 2;
                    *(float2*)(dst + e) = make_float2(acc[mt][nt][half * 2],
                                                      acc[mt][nt][half * 2 + 1]);
                }
            }
        }
    } else {
        #pragma unroll
        for (int mt = 0; mt < 2; mt++) {
            const int m0 = bm + wm + mt * 16 + g;
            #pragma unroll
            for (int half = 0; half < 2; half++) {
                const int m = m0 + half * 8;
                float* dst = Y + (size_t)m * 1024;
                #pragma unroll
                for (int nt = 0; nt < 8; nt++) {
                    const int gn = gnw + nt * 8 + tg * 2;
                    float2 bb = *(const float2*)(bias + gn);
                    *(float2*)(dst + gn) = make_float2(acc[mt][nt][half * 2] + bb.x,
                                                       acc[mt][nt][half * 2 + 1] + bb.y);
                }
            }
        }
    }
}

// =============================================================
// Kernel 2: per-(b,h) partial M = K^T V over an S-chunk of 256 rows.
// float4 smem reads (Ks broadcast, Vs conflict-free).
// =============================================================
__global__ __launch_bounds__(256) void k2_kv()
{
    const int bh = blockIdx.x;
    const int sc = blockIdx.y;
    const float* K = g_K + (bh * S_LEN + sc * 256) * HS;
    const float* V = g_V + (bh * S_LEN + sc * 256) * HS;

    __shared__ float Ks[32][64];
    __shared__ float Vs[32][64];
    const int tid = threadIdx.x;
    const int tx = tid & 15, ty = tid >> 4;

    float acc[4][4] = {};

    for (int s0 = 0; s0 < 256; s0 += 32) {
        #pragma unroll
        for (int i = 0; i < 2; i++) {
            int idx = (tid + i * 256) * 4;           // 2048 floats each array
            int r = idx >> 6, c = idx & 63;
            *(float4*)&Ks[r][c] = *(const float4*)(K + (s0 + r) * HS + c);
            *(float4*)&Vs[r][c] = *(const float4*)(V + (s0 + r) * HS + c);
        }
        __syncthreads();
        #pragma unroll
        for (int s = 0; s < 32; s++) {
            float4 a4 = *(const float4*)&Ks[s][ty * 4];
            float4 b4 = *(const float4*)&Vs[s][tx * 4];
            float a[4] = {a4.x, a4.y, a4.z, a4.w};
            float b[4] = {b4.x, b4.y, b4.z, b4.w};
            #pragma unroll
            for (int i = 0; i < 4; i++)
                #pragma unroll
                for (int j = 0; j < 4; j++)
                    acc[i][j] += a[i] * b[j];
        }
        __syncthreads();
    }

    float* P = g_Mpart + (bh * 8 + sc) * (HS * HS);
    #pragma unroll
    for (int i = 0; i < 4; i++)
        #pragma unroll
        for (int j = 0; j < 4; j++)
            P[(ty * 4 + i) * HS + tx * 4 + j] = acc[i][j];
}

__global__ __launch_bounds__(256) void k2_reduce()
{
    int i = blockIdx.x * 256 + threadIdx.x;
    int bh = i >> 12;
    int o  = i & 4095;
    float s = 0.f;
    #pragma unroll
    for (int c = 0; c < 8; c++)
        s += g_Mpart[(bh * 8 + c) * 4096 + o];
    g_M[i] = s * 0.125f;
}

// =============================================================
// Kernel 3 (tensor): A[b,s,h*64+f] = sum_e V[b,h,s,e] * M[b,h,e,f]
// CTA: 128 s-rows x 64 f, K=64. 8 warps, warp tile 32x32.
// V and M tf32-rounded at staging; output rounded in epilogue.
// Smem pitch 68 (68%32==4 -> banks 4g+tg conflict-free).
// =============================================================
#define K3P 68
__global__ __launch_bounds__(256) void k3_av()
{
    __shared__ float Vs[128][K3P];
    __shared__ float Mt[64][K3P];          // Mt[f][e] = M[e][f]

    const int bh = blockIdx.x;
    const int s0 = blockIdx.y * 128;
    const int tid = threadIdx.x, wid = tid >> 5, lane = tid & 31;
    const int g = lane >> 2, tg = lane & 3;

    // stage V block (128 x 64), tf32-rounded
    const float* Vg = g_V + (size_t)(bh * S_LEN + s0) * HS;
    #pragma unroll
    for (int i = 0; i < 8; i++) {
        int idx = tid + i * 256;            // 2048 float4-slots
        int r = idx >> 4, c4 = idx & 15;
        float4 v = *(const float4*)(Vg + r * HS + c4 * 4);
        *(float4*)&Vs[r][c4 * 4] = make_float4(f2tf32(v.x), f2tf32(v.y),
                                               f2tf32(v.z), f2tf32(v.w));
    }
    // stage M transposed (Mt[f][e]), tf32-rounded
    const float* Mg = g_M + bh * 4096;
    #pragma unroll
    for (int i = 0; i < 16; i++) {
        int idx = tid + i * 256;
        int e = idx >> 6, f = idx & 63;
        Mt[f][e] = f2tf32(Mg[idx]);
    }
    __syncthreads();

    const int wm = (wid & 3) * 32;        // 4 warps along s
    const int wn = (wid >> 2) * 32;       // 2 warps along f

    float acc[2][4][4] = {};
    #pragma unroll
    for (int ks = 0; ks < 8; ks++) {
        const int k = ks * 8 + tg;
        float a[2][4], b[4][2];
        #pragma unroll
        for (int mt = 0; mt < 2; mt++) {
            const float* p = &Vs[wm + mt * 16 + g][k];
            a[mt][0] = p[0];
            a[mt][1] = p[8 * K3P];
            a[mt][2] = p[4];
            a[mt][3] = p[8 * K3P + 4];
        }
        #pragma unroll
        for (int nt = 0; nt < 4; nt++) {
            const float* p = &Mt[wn + nt * 8 + g][k];
            b[nt][0] = p[0];
            b[nt][1] = p[4];
        }
        #pragma unroll
        for (int mt = 0; mt < 2; mt++)
            #pragma unroll
            for (int nt = 0; nt < 4; nt++)
                mma8(acc[mt][nt], a[mt], b[nt]);
    }

    // epilogue: write g_A rows (b,s), cols h*64 + f, tf32-rounded
    const int b = bh >> 4, h = bh & 15;
    #pragma unroll
    for (int mt = 0; mt < 2; mt++) {
        const int r0 = wm + mt * 16 + g;
        #pragma unroll
        for (int half = 0; half < 2; half++) {
            const int s = s0 + r0 + half * 8;
            float* dst = g_A + (size_t)(b * S_LEN + s) * D_DIM + h * HS;
            #pragma unroll
            for (int nt = 0; nt < 4; nt++) {
                const int f = wn + nt * 8 + tg * 2;
                *(float2*)(dst + f) = make_float2(f2tf32(acc[mt][nt][half * 2]),
                                                  f2tf32(acc[mt][nt][half * 2 + 1]));
            }
        }
    }
}

// =============================================================
extern "C" void kernel_launch(void* const* d_in, const int* in_sizes, int n_in,
                              void* d_out, int out_size)
{
    const float* x   = (const float*)d_in[0];
    const float* Wk  = (const float*)d_in[1];
    const float* Wv  = (const float*)d_in[2];
    const float* Wp  = (const float*)d_in[3];
    const float* bp  = (const float*)d_in[4];
    float* Y = (float*)d_out;

    cudaFuncSetAttribute(gemm_mma, cudaFuncAttributeMaxDynamicSharedMemorySize, GEMM_SMEM);

    xcvt<<<4096, 256>>>(x);                            // x -> tf32
    tW  <<<dim3(32, 2, 32), dim3(32, 8)>>>(Wk, Wv);    // [Wk|Wv] -> K-major tf32
    tWp <<<dim3(32, 32),    dim3(32, 8)>>>(Wp);        // Wproj^T -> K-major tf32

    gemm_mma<<<dim3(16, 32), 256, GEMM_SMEM>>>(bp, Y, 0);  // K,V projection
    k2_kv    <<<dim3(32, 8), 256>>>();                     // partial K^T V
    k2_reduce<<<512, 256>>>();                             // reduce + scale
    k3_av    <<<dim3(32, 16), 256>>>();                    // V @ M -> g_A (tensor)
    gemm_mma<<<dim3(8, 32), 256, GEMM_SMEM>>>(bp, Y, 1);   // Y = A@Wp + b
}

// round 9
// speedup vs baseline: 3.6817x; 1.0967x over previous
#include <cuda_runtime.h>

// B=2, S=2048, D=1024, H=16, HS=64
// out = V @ (K^T @ V) / 8 per (b,h)   (no softmax, Q==V)
// mma.sync m16n8k8 tf32 + cp.async.
// R9: K-permuted operand layout -> LDS.64 fragment loads (half the LDS
// instructions), single __syncthreads per k-iter (distance-2 prefetch),
// R7 warp tiling (64x64) which had the best MMA:LDS ratio.

#define S_LEN 2048
#define D_DIM 1024
#define HS    64
#define BH    32
#define MROWS 4096

// k-group permutation: store order [k0,k4,k1,k5,k2,k6,k3,k7] so fragment
// pairs (tg, tg+4) are adjacent -> LDS.64. Same perm on A and B => exact.
#define PERMK(i) (((i) & ~7) | ((((i) & 7) < 4) ? (((i) & 7) << 1) \
                                                : ((((i) & 7) - 4) * 2 + 1)))

// ---------------- scratch (no allocs allowed) ----------------
__device__ float g_K[BH * S_LEN * HS];        // [B,H,S,HS] fp32, natural
__device__ float g_V[BH * S_LEN * HS];        // [B,H,S,HS] fp32, natural
__device__ float g_Mpart[BH * 8 * HS * HS];
__device__ float g_M[BH * HS * HS];
__device__ float g_A[MROWS * D_DIM];          // tf32, k-PERMUTED columns
__device__ float g_Xtf[MROWS * D_DIM];        // x tf32, k-PERMUTED columns
__device__ float g_Wt[2048 * 1024];           // [Wk|Wv] K-major, k-PERMUTED
__device__ float g_Wpt[1024 * 1024];          // Wproj^T K-major, k-PERMUTED

// =============================================================
// helpers
// =============================================================
__device__ __forceinline__ float f2tf32(float f) {
    unsigned u;
    asm("cvt.rna.tf32.f32 %0, %1;" : "=r"(u) : "f"(f));
    return __uint_as_float(u);
}

__device__ __forceinline__ void cp16(void* dst, const void* src) {
    unsigned d;
    asm("{ .reg .u64 t; cvta.to.shared.u64 t, %1; cvt.u32.u64 %0, t; }"
        : "=r"(d) : "l"(dst));
    asm volatile("cp.async.cg.shared.global [%0], [%1], 16;" :: "r"(d), "l"(src));
}

__device__ __forceinline__ void mma8(float* d, const float* a, const float* b) {
    asm volatile(
        "mma.sync.aligned.m16n8k8.row.col.f32.tf32.tf32.f32 "
        "{%0,%1,%2,%3}, {%4,%5,%6,%7}, {%8,%9}, {%0,%1,%2,%3};"
        : "+f"(d[0]), "+f"(d[1]), "+f"(d[2]), "+f"(d[3])
        : "r"(__float_as_uint(a[0])), "r"(__float_as_uint(a[1])),
          "r"(__float_as_uint(a[2])), "r"(__float_as_uint(a[3])),
          "r"(__float_as_uint(b[0])), "r"(__float_as_uint(b[1])));
}

// =============================================================
// x -> tf32, k-permuted. One thread per 8-group.
// out slots: [v0.x, v1.x, v0.y, v1.y] [v0.z, v1.z, v0.w, v1.w]
// =============================================================
__global__ __launch_bounds__(256) void xcvt(const float* __restrict__ x)
{
    int base = (blockIdx.x * 256 + threadIdx.x) * 8;
    float4 v0 = *(const float4*)(x + base);
    float4 v1 = *(const float4*)(x + base + 4);
    *(float4*)(g_Xtf + base) = make_float4(f2tf32(v0.x), f2tf32(v1.x),
                                           f2tf32(v0.y), f2tf32(v1.y));
    *(float4*)(g_Xtf + base + 4) = make_float4(f2tf32(v0.z), f2tf32(v1.z),
                                               f2tf32(v0.w), f2tf32(v1.w));
}

// =============================================================
// Weight transposes -> K-major rows, tf32, k-permuted columns
// =============================================================
__global__ __launch_bounds__(256) void tW(const float* __restrict__ Wk,
                                          const float* __restrict__ Wv)
{
    __shared__ float tile[32][33];
    const int hh = blockIdx.z;
    const int x0 = blockIdx.x * 32;         // d tile (k-dim)
    const int y0 = blockIdx.y * 32;         // e tile
    const int tx = threadIdx.x, ty = threadIdx.y;
    const float* W = (hh < 16) ? Wk : Wv;
    const int h = hh & 15;
    #pragma unroll
    for (int j = 0; j < 4; j++)
        tile[ty + 8 * j][tx] = W[h * 65536 + (x0 + ty + 8 * j) * 64 + y0 + tx];
    __syncthreads();
    const int dp = x0 + PERMK(tx);
    #pragma unroll
    for (int j = 0; j < 4; j++)
        g_Wt[(hh * 64 + y0 + ty + 8 * j) * 1024 + dp] = f2tf32(tile[tx][ty + 8 * j]);
}

__global__ __launch_bounds__(256) void tWp(const float* __restrict__ Wp)
{
    __shared__ float tile[32][33];
    const int x0 = blockIdx.x * 32;   // n tile
    const int y0 = blockIdx.y * 32;   // k tile
    const int tx = threadIdx.x, ty = threadIdx.y;
    #pragma unroll
    for (int j = 0; j < 4; j++)
        tile[ty + 8 * j][tx] = Wp[(y0 + ty + 8 * j) * 1024 + x0 + tx];
    __syncthreads();
    const int kp = y0 + PERMK(tx);
    #pragma unroll
    for (int j = 0; j < 4; j++)
        g_Wpt[(x0 + ty + 8 * j) * 1024 + kp] = f2tf32(tile[tx][ty + 8 * j]);
}

// =============================================================
// tf32 mma.sync GEMM: C[4096, N] = A[4096,1024] @ B^T (k-permuted operands)
// BM=128, BN=256, BK=32, 3-stage / distance-2 prefetch, ONE sync per iter.
// 8 warps, warp tile 64x64. PITCH=40 (==8 mod 32) -> LDS.64 conflict-free.
// mode 0: A=g_Xtf, B=g_Wt, scatter K/V.  mode 1: A=g_A, B=g_Wpt, Y + bias.
// =============================================================
#define BMt 128
#define BNt 256
#define BKt 32
#define PITCH 40
#define SA_BYTES (BMt * PITCH * 4)             // 20480
#define SB_BYTES (BNt * PITCH * 4)             // 40960
#define STAGE_BYTES (SA_BYTES + SB_BYTES)      // 61440
#define GEMM_SMEM (3 * STAGE_BYTES)            // 184320

__global__ __launch_bounds__(256, 1)
void gemm_mma(const float* __restrict__ bias,
              float* __restrict__ Y,
              int mode)
{
    extern __shared__ __align__(16) char sm[];
    const int tid = threadIdx.x, wid = tid >> 5, lane = tid & 31;
    const int g = lane >> 2, tg = lane & 3;
    const int bm = blockIdx.y * BMt, bn = blockIdx.x * BNt;

    const float* Ag = ((mode == 0) ? g_Xtf : g_A) + (size_t)bm * 1024;
    const float* Bg = ((mode == 0) ? g_Wt : g_Wpt) + (size_t)bn * 1024;

    auto prefetch = [&](int kc) {
        char* sA = sm + (kc % 3) * STAGE_BYTES;
        char* sB = sA + SA_BYTES;
        const float* As = Ag + kc * BKt;
        const float* Bs = Bg + kc * BKt;
        #pragma unroll
        for (int i = 0; i < 4; i++) {
            int idx = tid + i * 256;
            int m = idx >> 3, k4 = idx & 7;
            cp16(sA + m * (PITCH * 4) + k4 * 16, As + (size_t)m * 1024 + k4 * 4);
        }
        #pragma unroll
        for (int i = 0; i < 8; i++) {
            int idx = tid + i * 256;
            int n = idx >> 3, k4 = idx & 7;
            cp16(sB + n * (PITCH * 4) + k4 * 16, Bs + (size_t)n * 1024 + k4 * 4);
        }
        asm volatile("cp.async.commit_group;" ::: "memory");
    };

    prefetch(0); prefetch(1);

    const int wm = (wid & 1) * 64;       // 2 warps along M
    const int wn = (wid >> 1) * 64;      // 4 warps along N

    float acc[4][8][4];
    #pragma unroll
    for (int mt = 0; mt < 4; mt++)
        #pragma unroll
        for (int nt = 0; nt < 8; nt++)
            #pragma unroll
            for (int q = 0; q < 4; q++) acc[mt][nt][q] = 0.f;

    for (int kc = 0; kc < 32; kc++) {
        const float* sA = (const float*)(sm + (kc % 3) * STAGE_BYTES);
        const float* sB = (const float*)((const char*)sA + SA_BYTES);
        // stage kc must be complete: issued groups = min(32, kc+2),
        // so pending allowed = 1 except on the last iteration.
        if (kc < 31) asm volatile("cp.async.wait_group 1;" ::: "memory");
        else         asm volatile("cp.async.wait_group 0;" ::: "memory");
        __syncthreads();
        // buffer (kc+2)%3 was last read at iter kc-1; all warps are past it.
        if (kc + 2 < 32) prefetch(kc + 2);

        #pragma unroll
        for (int ks = 0; ks < 4; ks++) {
            const int kslot = ks * 8 + 2 * tg;      // permuted: (tg, tg+4) pair
            float a[4][4], b[8][2];
            #pragma unroll
            for (int mt = 0; mt < 4; mt++) {
                const float* p = sA + (wm + mt * 16 + g) * PITCH + kslot;
                float2 lo = *(const float2*)p;              // rows g
                float2 hi = *(const float2*)(p + 8 * PITCH); // rows g+8
                a[mt][0] = lo.x; a[mt][1] = hi.x;
                a[mt][2] = lo.y; a[mt][3] = hi.y;
            }
            #pragma unroll
            for (int nt = 0; nt < 8; nt++) {
                float2 bb = *(const float2*)(sB + (wn + nt * 8 + g) * PITCH + kslot);
                b[nt][0] = bb.x; b[nt][1] = bb.y;
            }
            #pragma unroll
            for (int mt = 0; mt < 4; mt++)
                #pragma unroll
                for (int nt = 0; nt < 8; nt++)
                    mma8(acc[mt][nt], a[mt], b[nt]);
        }
    }

    // ---- epilogue ----
    // C frag: c0 (row g, col 2tg), c1 (+1), c2 (row g+8, col 2tg), c3 (+1)
    const int gnw = bn + wn;                 // 64-aligned -> exactly 1 head
    if (mode == 0) {
        const int isK = (gnw < 1024);
        const int h = (gnw & 1023) >> 6;
        float* base = (isK ? g_K : g_V);
        #pragma unroll
        for (int mt = 0; mt < 4; mt++) {
            const int m0 = bm + wm + mt * 16 + g;
            #pragma unroll
            for (int half = 0; half < 2; half++) {
                const int m = m0 + half * 8;
                const int b = m >> 11, s = m & 2047;
                float* dst = base + (size_t)((b * 16 + h) * 2048 + s) * 64;
                #pragma unroll
                for (int nt = 0; nt < 8; nt++) {
                    const int e = nt * 8 + tg * 2;
                    *(float2*)(dst + e) = make_float2(acc[mt][nt][half * 2],
                                                      acc[mt][nt][half * 2 + 1]);
                }
            }
        }
    } else {
        #pragma unroll
        for (int mt = 0; mt < 4; mt++) {
            const int m0 = bm + wm + mt * 16 + g;
            #pragma unroll
            for (int half = 0; half < 2; half++) {
                const int m = m0 + half * 8;
                float* dst = Y + (size_t)m * 1024;
                #pragma unroll
                for (int nt = 0; nt < 8; nt++) {
                    const int gn = gnw + nt * 8 + tg * 2;
                    float2 bb = *(const float2*)(bias + gn);
                    *(float2*)(dst + gn) = make_float2(acc[mt][nt][half * 2] + bb.x,
                                                       acc[mt][nt][half * 2 + 1] + bb.y);
                }
            }
        }
    }
}

// =============================================================
// Kernel 2: per-(b,h) partial M = K^T V over an S-chunk of 256 rows.
// =============================================================
__global__ __launch_bounds__(256) void k2_kv()
{
    const int bh = blockIdx.x;
    const int sc = blockIdx.y;
    const float* K = g_K + (bh * S_LEN + sc * 256) * HS;
    const float* V = g_V + (bh * S_LEN + sc * 256) * HS;

    __shared__ float Ks[32][64];
    __shared__ float Vs[32][64];
    const int tid = threadIdx.x;
    const int tx = tid & 15, ty = tid >> 4;

    float acc[4][4] = {};

    for (int s0 = 0; s0 < 256; s0 += 32) {
        #pragma unroll
        for (int i = 0; i < 2; i++) {
            int idx = (tid + i * 256) * 4;
            int r = idx >> 6, c = idx & 63;
            *(float4*)&Ks[r][c] = *(const float4*)(K + (s0 + r) * HS + c);
            *(float4*)&Vs[r][c] = *(const float4*)(V + (s0 + r) * HS + c);
        }
        __syncthreads();
        #pragma unroll
        for (int s = 0; s < 32; s++) {
            float4 a4 = *(const float4*)&Ks[s][ty * 4];
            float4 b4 = *(const float4*)&Vs[s][tx * 4];
            float a[4] = {a4.x, a4.y, a4.z, a4.w};
            float b[4] = {b4.x, b4.y, b4.z, b4.w};
            #pragma unroll
            for (int i = 0; i < 4; i++)
                #pragma unroll
                for (int j = 0; j < 4; j++)
                    acc[i][j] += a[i] * b[j];
        }
        __syncthreads();
    }

    float* P = g_Mpart + (bh * 8 + sc) * (HS * HS);
    #pragma unroll
    for (int i = 0; i < 4; i++)
        #pragma unroll
        for (int j = 0; j < 4; j++)
            P[(ty * 4 + i) * HS + tx * 4 + j] = acc[i][j];
}

__global__ __launch_bounds__(256) void k2_reduce()
{
    int i = blockIdx.x * 256 + threadIdx.x;
    int bh = i >> 12;
    int o  = i & 4095;
    float s = 0.f;
    #pragma unroll
    for (int c = 0; c < 8; c++)
        s += g_Mpart[(bh * 8 + c) * 4096 + o];
    g_M[i] = s * 0.125f;
}

// =============================================================
// Kernel 3 (tensor): A[b,s,h*64+f] = sum_e V[b,h,s,e] * M[b,h,e,f]
// Same internals as R8 (validated); epilogue now writes k-PERMUTED f columns
// because g_A feeds GEMM2's k-dim.
// =============================================================
#define K3P 68
__global__ __launch_bounds__(256) void k3_av()
{
    __shared__ float Vs[128][K3P];
    __shared__ float Mt[64][K3P];          // Mt[f][e] = M[e][f]

    const int bh = blockIdx.x;
    const int s0 = blockIdx.y * 128;
    const int tid = threadIdx.x, wid = tid >> 5, lane = tid & 31;
    const int g = lane >> 2, tg = lane & 3;

    const float* Vg = g_V + (size_t)(bh * S_LEN + s0) * HS;
    #pragma unroll
    for (int i = 0; i < 8; i++) {
        int idx = tid + i * 256;
        int r = idx >> 4, c4 = idx & 15;
        float4 v = *(const float4*)(Vg + r * HS + c4 * 4);
        *(float4*)&Vs[r][c4 * 4] = make_float4(f2tf32(v.x), f2tf32(v.y),
                                               f2tf32(v.z), f2tf32(v.w));
    }
    const float* Mg = g_M + bh * 4096;
    #pragma unroll
    for (int i = 0; i < 16; i++) {
        int idx = tid + i * 256;
        int e = idx >> 6, f = idx & 63;
        Mt[f][e] = f2tf32(Mg[idx]);
    }
    __syncthreads();

    const int wm = (wid & 3) * 32;        // 4 warps along s
    const int wn = (wid >> 2) * 32;       // 2 warps along f

    float acc[2][4][4] = {};
    #pragma unroll
    for (int ks = 0; ks < 8; ks++) {
        const int k = ks * 8 + tg;
        float a[2][4], b[4][2];
        #pragma unroll
        for (int mt = 0; mt < 2; mt++) {
            const float* p = &Vs[wm + mt * 16 + g][k];
            a[mt][0] = p[0];
            a[mt][1] = p[8 * K3P];
            a[mt][2] = p[4];
            a[mt][3] = p[8 * K3P + 4];
        }
        #pragma unroll
        for (int nt = 0; nt < 4; nt++) {
            const float* p = &Mt[wn + nt * 8 + g][k];
            b[nt][0] = p[0];
            b[nt][1] = p[4];
        }
        #pragma unroll
        for (int mt = 0; mt < 2; mt++)
            #pragma unroll
            for (int nt = 0; nt < 4; nt++)
                mma8(acc[mt][nt], a[mt], b[nt]);
    }

    const int b = bh >> 4, h = bh & 15;
    #pragma unroll
    for (int mt = 0; mt < 2; mt++) {
        const int r0 = wm + mt * 16 + g;
        #pragma unroll
        for (int half = 0; half < 2; half++) {
            const int s = s0 + r0 + half * 8;
            float* dst = g_A + (size_t)(b * S_LEN + s) * D_DIM + h * HS;
            #pragma unroll
            for (int nt = 0; nt < 4; nt++) {
                const int f = wn + nt * 8 + tg * 2;          // logical
                dst[PERMK(f)]     = f2tf32(acc[mt][nt][half * 2]);
                dst[PERMK(f + 1)] = f2tf32(acc[mt][nt][half * 2 + 1]);
            }
        }
    }
}

// =============================================================
extern "C" void kernel_launch(void* const* d_in, const int* in_sizes, int n_in,
                              void* d_out, int out_size)
{
    const float* x   = (const float*)d_in[0];
    const float* Wk  = (const float*)d_in[1];
    const float* Wv  = (const float*)d_in[2];
    const float* Wp  = (const float*)d_in[3];
    const float* bp  = (const float*)d_in[4];
    float* Y = (float*)d_out;

    cudaFuncSetAttribute(gemm_mma, cudaFuncAttributeMaxDynamicSharedMemorySize, GEMM_SMEM);

    xcvt<<<2048, 256>>>(x);                            // x -> tf32, permuted
    tW  <<<dim3(32, 2, 32), dim3(32, 8)>>>(Wk, Wv);    // [Wk|Wv] -> K-major tf32
    tWp <<<dim3(32, 32),    dim3(32, 8)>>>(Wp);        // Wproj^T -> K-major tf32

    gemm_mma<<<dim3(8, 32), 256, GEMM_SMEM>>>(bp, Y, 0);   // K,V projection
    k2_kv    <<<dim3(32, 8), 256>>>();                     // partial K^T V
    k2_reduce<<<512, 256>>>();                             // reduce + scale
    k3_av    <<<dim3(32, 16), 256>>>();                    // V @ M -> g_A (tensor)
    gemm_mma<<<dim3(4, 32), 256, GEMM_SMEM>>>(bp, Y, 1);   // Y = A@Wp + b
}